// round 4
// baseline (speedup 1.0000x reference)
#include <cuda_runtime.h>
#include <cstdint>

#define NT 256
#define ROWP 129

// Pool offsets (in floats)
#define OFF_U    0        // 128 x ROWP = 16512   (phase A-B)
#define OFF_H1   16512    // 64 x ROWP  = 8256    (phase B)
#define OFF_MN   24768    // 64 x ROWP  = 8256    (phase B-D)
#define OFF_WSH  33024    // 8192 weight staging  (all phases)
#define OFF_RES  0        // 64 x ROWP  (phase D-E, reuses U)
#define OFF_SIG  16512    // 64 x ROWP  (phase D, reuses H1)
#define OFF_GB   8256     // 192 x ROWP = 24768 (phase E, reuses U-tail+H1+MN)
#define OFF_HT   41216    // 64 x ROWP  = 8256 (persistent)
#define SMEM_FLOATS 49472 // 197888 bytes dynamic

__device__ float g_adj[2048];

static __device__ __forceinline__ float clipf(float x, float lo, float hi) {
    return fminf(fmaxf(x, lo), hi);
}
static __device__ __forceinline__ float sigf(float x) {
    return 1.0f / (1.0f + expf(-x));
}

// ---------------------------------------------------------------------------
// Kernel 1: adj[k][d] = clip( sum_c a0[c]*graphs[k,c,d] / max(sum(a0),1), -5, 5 )
// a0 = one_hot[qt[0]], sparse (~5 nonzeros). grid=(2), block=1024.
// ---------------------------------------------------------------------------
__global__ void adj_kernel(const int* __restrict__ qt,
                           const float* __restrict__ one_hot,
                           const float* __restrict__ graphs)
{
    __shared__ int nzIdx[1024];
    __shared__ int nzCnt;
    const int k = blockIdx.x;
    const int tid = threadIdx.x;
    if (tid == 0) nzCnt = 0;
    __syncthreads();
    const int q0 = __ldg(&qt[0]);
    const float v = __ldg(&one_hot[(size_t)q0 * 1024 + tid]);
    if (v > 0.5f) { int p = atomicAdd(&nzCnt, 1); nzIdx[p] = tid; }
    __syncthreads();
    const int cnt = nzCnt;
    const float denom = fmaxf((float)cnt, 1.0f);
    float s = 0.0f;
    for (int t = 0; t < cnt; ++t)
        s += __ldg(&graphs[((size_t)k * 1024 + (size_t)nzIdx[t]) * 1024 + tid]);
    g_adj[k * 1024 + tid] = clipf(s / denom, -5.0f, 5.0f);
}

// ---------------------------------------------------------------------------
// Block GEMM tile: M=128 rows, N=64 cols, thread (tx 0..15, ty 0..15) owns
// 8 rows x 4 cols. A is [K][ROWP] in shared (row fastest), W is [K][64].
// ---------------------------------------------------------------------------
static __device__ __forceinline__ void gemm64(const float* __restrict__ A,
                                              const float* __restrict__ W,
                                              int K, int tx, int ty,
                                              float acc[8][4])
{
#pragma unroll
    for (int rr = 0; rr < 8; ++rr)
#pragma unroll
        for (int cc = 0; cc < 4; ++cc) acc[rr][cc] = 0.0f;

    const float* Ap = A + ty * 8;
    const float* Wp = W + tx * 4;
#pragma unroll 4
    for (int k = 0; k < K; ++k) {
        const float4 bv = *reinterpret_cast<const float4*>(Wp + k * 64);
        float a[8];
#pragma unroll
        for (int rr = 0; rr < 8; ++rr) a[rr] = Ap[k * ROWP + rr];
#pragma unroll
        for (int rr = 0; rr < 8; ++rr) {
            acc[rr][0] = fmaf(a[rr], bv.x, acc[rr][0]);
            acc[rr][1] = fmaf(a[rr], bv.y, acc[rr][1]);
            acc[rr][2] = fmaf(a[rr], bv.z, acc[rr][2]);
            acc[rr][3] = fmaf(a[rr], bv.w, acc[rr][3]);
        }
    }
}

// Stage n4 float4s of contiguous weights into shared.
static __device__ __forceinline__ void stage4(const float* __restrict__ g,
                                              float* __restrict__ s,
                                              int n4, int tid)
{
    const float4* gs = reinterpret_cast<const float4*>(g);
    float4* ss = reinterpret_cast<float4*>(s);
    for (int i = tid; i < n4; i += NT) ss[i] = __ldg(gs + i);
}

// Stage a 64-col slice [j0, j0+64) of a (64 x 192) row-major matrix.
static __device__ __forceinline__ void stage_slice192(const float* __restrict__ g,
                                                      int j0, float* __restrict__ s,
                                                      int tid)
{
    for (int i = tid; i < 64 * 16; i += NT) {
        const int k  = i >> 4;
        const int j4 = i & 15;
        const float4 v = __ldg(reinterpret_cast<const float4*>(&g[k * 192 + j0]) + j4);
        reinterpret_cast<float4*>(s)[k * 16 + j4] = v;
    }
}

// ---------------------------------------------------------------------------
// Main fused kernel: one block per (b, 128-row c-tile).
// ---------------------------------------------------------------------------
extern __shared__ float dynsmem[];

__global__ void __launch_bounds__(NT, 1)
main_kernel(const int*   __restrict__ qt,
            const float* __restrict__ ht,
            const float* __restrict__ one_hot,
            const float* __restrict__ kcE,
            const float* __restrict__ nwp,
            const float* __restrict__ Ws1, const float* __restrict__ bs1,
            const float* __restrict__ Ws2, const float* __restrict__ bs2,
            const float* __restrict__ Wn1, const float* __restrict__ bn1,
            const float* __restrict__ Wn2, const float* __restrict__ bn2,
            const float* __restrict__ ea_w,
            const float* __restrict__ We,  const float* __restrict__ be,
            const float* __restrict__ Wa,  const float* __restrict__ ba,
            const float* __restrict__ W_ih, const float* __restrict__ b_ih,
            const float* __restrict__ W_hh, const float* __restrict__ b_hh,
            const float* __restrict__ Wpv, const float* __restrict__ bp,
            float* __restrict__ out)
{
    const int tid = threadIdx.x;
    const int tx = tid & 15;
    const int ty = tid >> 4;
    const int c0 = blockIdx.x * 128;
    const int b  = blockIdx.y;

    float* pool = dynsmem;
    float* HT   = dynsmem + OFF_HT;   // raw ht, transposed [f][row]
    float* U    = pool + OFF_U;       // clip(t,-5,5), transposed [k][row]
    float* Wsh  = pool + OFF_WSH;
    float* H1   = pool + OFF_H1;
    float* MN   = pool + OFF_MN;

    __shared__ float maskS[128], adj0S[128], adj1S[128], eaS[128], yS[128], WpS[64];
    __shared__ float selfH1[8][64];
    __shared__ int selfRows[128];
    __shared__ int selfCnt;

    if (tid == 0) selfCnt = 0;
    __syncthreads();

    // ---------------- Phase A: gather per-row metadata, build HT / U ----------
    const int qb = __ldg(&qt[b]);
    if (tid < 128) {
        const int row = tid;
        const int c = c0 + row;
        const float m = __ldg(&one_hot[(size_t)qb * 1024 + c]);
        maskS[row] = m;
        adj0S[row] = g_adj[c];
        adj1S[row] = g_adj[1024 + c];
        eaS[row]   = __ldg(&ea_w[c]);
        if (m > 0.5f) { int p = atomicAdd(&selfCnt, 1); selfRows[p] = row; }
    }
    if (tid < 64) WpS[tid] = __ldg(&Wpv[tid]);

    for (int i = tid; i < 128 * 16; i += NT) {
        const int row = i >> 4;
        const int f4  = i & 15;
        const float4 v = __ldg(reinterpret_cast<const float4*>(
                               &ht[((size_t)b * 1024 + c0 + row) * 64]) + f4);
        const int f = f4 * 4;
        HT[(f + 0) * ROWP + row] = v.x;
        HT[(f + 1) * ROWP + row] = v.y;
        HT[(f + 2) * ROWP + row] = v.z;
        HT[(f + 3) * ROWP + row] = v.w;
        U[(f + 0) * ROWP + row] = clipf(v.x, -5.0f, 5.0f);
        U[(f + 1) * ROWP + row] = clipf(v.y, -5.0f, 5.0f);
        U[(f + 2) * ROWP + row] = clipf(v.z, -5.0f, 5.0f);
        U[(f + 3) * ROWP + row] = clipf(v.w, -5.0f, 5.0f);
    }
    for (int i = tid; i < 128 * 16; i += NT) {
        const int row = i >> 4;
        const int f4  = i & 15;
        const float4 v = __ldg(reinterpret_cast<const float4*>(
                               &kcE[(size_t)(c0 + row) * 64]) + f4);
        const int f = 64 + f4 * 4;
        U[(f + 0) * ROWP + row] = clipf(v.x, -5.0f, 5.0f);
        U[(f + 1) * ROWP + row] = clipf(v.y, -5.0f, 5.0f);
        U[(f + 2) * ROWP + row] = clipf(v.z, -5.0f, 5.0f);
        U[(f + 3) * ROWP + row] = clipf(v.w, -5.0f, 5.0f);
    }
    __syncthreads();

    const float w = clipf(__ldg(&nwp[0]), 0.1f, 0.9f);
    float acc[8][4];

    // ---------------- Phase B: neighbor MLPs (mask==0 path, valid for all) ----
    // For mask==0, neigh_ht = [0, clip(t)] => only Wn1[k][128:256] contributes.
#pragma unroll 1
    for (int k = 0; k < 2; ++k) {
        stage4(Wn1 + (size_t)k * 16384 + 8192, Wsh, 2048, tid);   // 128x64
        __syncthreads();
        gemm64(U, Wsh, 128, tx, ty, acc);
        const float* bn1k = bn1 + k * 64;
#pragma unroll
        for (int cc = 0; cc < 4; ++cc) {
            const int j = tx * 4 + cc;
            const float bb = __ldg(&bn1k[j]);
#pragma unroll
            for (int rr = 0; rr < 8; ++rr)
                H1[j * ROWP + ty * 8 + rr] = fmaxf(acc[rr][cc] + bb, 0.0f);
        }
        __syncthreads();

        stage4(Wn2 + (size_t)k * 4096, Wsh, 1024, tid);           // 64x64
        __syncthreads();
        gemm64(H1, Wsh, 64, tx, ty, acc);
        const float* bn2k = bn2 + k * 64;
#pragma unroll
        for (int cc = 0; cc < 4; ++cc) {
            const int j = tx * 4 + cc;
            const float bb = __ldg(&bn2k[j]);
#pragma unroll
            for (int rr = 0; rr < 8; ++rr) {
                const int row = ty * 8 + rr;
                const float nb = fminf(fmaxf(acc[rr][cc] + bb, 0.0f), 5.0f); // clip(relu,±5)
                float* mp = &MN[j * ROWP + row];
                if (k == 0) {
                    *mp = clipf(adj0S[row] * nb, -5.0f, 5.0f);
                } else {
                    const float nf = w * (*mp) + (1.0f - w) * adj1S[row] * nb;
                    *mp = clipf(nf, -5.0f, 5.0f);   // |nf|<=5 so clip(±50) is no-op
                }
            }
        }
        __syncthreads();
    }

    // ---------------- Phase C: sparse self-MLP fixup for mask==1 rows ---------
    {
        const int nSelf = selfCnt;
        const int warpId = tid >> 5;
        const int lane = tid & 31;
        for (int s = warpId; s < nSelf; s += 8) {
            const int row = selfRows[s];
            const int c = c0 + row;
            float a1 = __ldg(&bs1[lane]);
            float a2 = __ldg(&bs1[lane + 32]);
#pragma unroll 4
            for (int i = 0; i < 64; ++i) {
                const float xi = HT[i * ROWP + row];
                a1 = fmaf(xi, __ldg(&Ws1[i * 64 + lane]), a1);
                a2 = fmaf(xi, __ldg(&Ws1[i * 64 + lane + 32]), a2);
            }
#pragma unroll 4
            for (int i = 0; i < 64; ++i) {
                const float xi = __ldg(&kcE[(size_t)c * 64 + i]);
                a1 = fmaf(xi, __ldg(&Ws1[(64 + i) * 64 + lane]), a1);
                a2 = fmaf(xi, __ldg(&Ws1[(64 + i) * 64 + lane + 32]), a2);
            }
            selfH1[warpId][lane]      = fmaxf(a1, 0.0f);
            selfH1[warpId][lane + 32] = fmaxf(a2, 0.0f);
            __syncwarp();
            float o1 = __ldg(&bs2[lane]);
            float o2 = __ldg(&bs2[lane + 32]);
#pragma unroll 4
            for (int i = 0; i < 64; ++i) {
                const float h = selfH1[warpId][i];
                o1 = fmaf(h, __ldg(&Ws2[i * 64 + lane]), o1);
                o2 = fmaf(h, __ldg(&Ws2[i * 64 + lane + 32]), o2);
            }
            MN[lane * ROWP + row]        = fminf(fmaxf(o1, 0.0f), 10.0f); // clip(relu,±10)
            MN[(lane + 32) * ROWP + row] = fminf(fmaxf(o2, 0.0f), 10.0f);
            __syncwarp();
        }
    }
    __syncthreads();

    // ---------------- Phase D: edge-attention residual ------------------------
    float* SIG = pool + OFF_SIG;
    float* RES = pool + OFF_RES;

    stage4(We, Wsh, 1024, tid);
    __syncthreads();
    gemm64(MN, Wsh, 64, tx, ty, acc);
#pragma unroll
    for (int cc = 0; cc < 4; ++cc) {
        const int j = tx * 4 + cc;
        const float bb = __ldg(&be[j]);
#pragma unroll
        for (int rr = 0; rr < 8; ++rr)
            SIG[j * ROWP + ty * 8 + rr] = sigf(acc[rr][cc] + bb);
    }
    __syncthreads();

    stage4(Wa, Wsh, 1024, tid);
    __syncthreads();
    gemm64(MN, Wsh, 64, tx, ty, acc);
#pragma unroll
    for (int cc = 0; cc < 4; ++cc) {
        const int j = tx * 4 + cc;
        const float bb = __ldg(&ba[j]);
#pragma unroll
        for (int rr = 0; rr < 8; ++rr) {
            const int row = ty * 8 + rr;
            const float mn = MN[j * ROWP + row];
            const float g  = eaS[row];
            RES[j * ROWP + row] =
                mn - g * SIG[j * ROWP + row] * mn + g * tanhf(acc[rr][cc] + bb);
        }
    }
    __syncthreads();

    // ---------------- Phase E: GRU + readout ----------------------------------
    float* GB = pool + OFF_GB;   // [192][ROWP]: gh then fused gates

    // gh = ht @ W_hh + b_hh   (3 passes of 64 cols)
#pragma unroll 1
    for (int p = 0; p < 3; ++p) {
        stage_slice192(W_hh, p * 64, Wsh, tid);
        __syncthreads();
        gemm64(HT, Wsh, 64, tx, ty, acc);
#pragma unroll
        for (int cc = 0; cc < 4; ++cc) {
            const int j = p * 64 + tx * 4 + cc;
            const float bb = __ldg(&b_hh[j]);
#pragma unroll
            for (int rr = 0; rr < 8; ++rr)
                GB[j * ROWP + ty * 8 + rr] = acc[rr][cc] + bb;
        }
        __syncthreads();
    }

    // gi passes 0,1: r = sigmoid(ir+hr), z = sigmoid(iz+hz), stored in place
#pragma unroll 1
    for (int p = 0; p < 2; ++p) {
        stage_slice192(W_ih, p * 64, Wsh, tid);
        __syncthreads();
        gemm64(RES, Wsh, 64, tx, ty, acc);
#pragma unroll
        for (int cc = 0; cc < 4; ++cc) {
            const int j = p * 64 + tx * 4 + cc;
            const float bb = __ldg(&b_ih[j]);
#pragma unroll
            for (int rr = 0; rr < 8; ++rr) {
                float* gp = &GB[j * ROWP + ty * 8 + rr];
                *gp = sigf(acc[rr][cc] + bb + *gp);
            }
        }
        __syncthreads();
    }

    // gi pass 2: n = tanh(in + r*hn); h_next = (1-z)*n + z*ht; y += h_next*Wp
    stage_slice192(W_ih, 128, Wsh, tid);
    __syncthreads();
    gemm64(RES, Wsh, 64, tx, ty, acc);
    {
        float yp[8];
#pragma unroll
        for (int rr = 0; rr < 8; ++rr) yp[rr] = 0.0f;
#pragma unroll
        for (int cc = 0; cc < 4; ++cc) {
            const int f = tx * 4 + cc;
            const float bb = __ldg(&b_ih[128 + f]);
            const float wp = WpS[f];
#pragma unroll
            for (int rr = 0; rr < 8; ++rr) {
                const int row = ty * 8 + rr;
                const float in_ = acc[rr][cc] + bb;
                const float r  = GB[f * ROWP + row];
                const float z  = GB[(64 + f) * ROWP + row];
                const float hn = GB[(128 + f) * ROWP + row];
                const float n  = tanhf(in_ + r * hn);
                const float hv = HT[f * ROWP + row];
                const float hnext = (1.0f - z) * n + z * hv;
                yp[rr] += hnext * wp;
            }
        }
        // reduce over the 16 tx lanes that share each row (within warp half)
#pragma unroll
        for (int rr = 0; rr < 8; ++rr) {
            float v = yp[rr];
#pragma unroll
            for (int off = 1; off < 16; off <<= 1)
                v += __shfl_xor_sync(0xffffffffu, v, off);
            if (tx == 0) yS[ty * 8 + rr] = v;
        }
    }
    __syncthreads();

    if (tid < 128) {
        const float yv = sigf(yS[tid] + __ldg(&bp[0]));
        out[(size_t)b * 1024 + c0 + tid] = yv;
    }
}

// ---------------------------------------------------------------------------
// Launcher
// ---------------------------------------------------------------------------
extern "C" void kernel_launch(void* const* d_in, const int* in_sizes, int n_in,
                              void* d_out, int out_size)
{
    // metadata order:
    // 0 xt (unused), 1 qt, 2 ht, 3 qt_kc_one_hot, 4 kc_embeddings, 5 graphs,
    // 6 neigh_weight, 7 Ws1, 8 bs1, 9 Ws2, 10 bs2, 11 Wn1, 12 bn1, 13 Wn2,
    // 14 bn2, 15 ea_w, 16 We, 17 be, 18 Wa, 19 ba, 20 W_ih, 21 b_ih,
    // 22 W_hh, 23 b_hh, 24 Wp, 25 bp
    const int*   qt     = (const int*)  d_in[1];
    const float* ht     = (const float*)d_in[2];
    const float* oh     = (const float*)d_in[3];
    const float* kcE    = (const float*)d_in[4];
    const float* graphs = (const float*)d_in[5];
    const float* nw     = (const float*)d_in[6];
    const float* Ws1    = (const float*)d_in[7];
    const float* bs1    = (const float*)d_in[8];
    const float* Ws2    = (const float*)d_in[9];
    const float* bs2    = (const float*)d_in[10];
    const float* Wn1    = (const float*)d_in[11];
    const float* bn1    = (const float*)d_in[12];
    const float* Wn2    = (const float*)d_in[13];
    const float* bn2    = (const float*)d_in[14];
    const float* ea     = (const float*)d_in[15];
    const float* We     = (const float*)d_in[16];
    const float* be     = (const float*)d_in[17];
    const float* Wa     = (const float*)d_in[18];
    const float* ba     = (const float*)d_in[19];
    const float* Wih    = (const float*)d_in[20];
    const float* bih    = (const float*)d_in[21];
    const float* Whh    = (const float*)d_in[22];
    const float* bhh    = (const float*)d_in[23];
    const float* Wp     = (const float*)d_in[24];
    const float* bp     = (const float*)d_in[25];
    float* out = (float*)d_out;

    adj_kernel<<<2, 1024>>>(qt, oh, graphs);

    const int smemBytes = SMEM_FLOATS * (int)sizeof(float); // 197888
    cudaFuncSetAttribute(main_kernel,
                         cudaFuncAttributeMaxDynamicSharedMemorySize, smemBytes);

    dim3 grid(8, 256);  // 8 c-tiles of 128, 256 batch rows
    main_kernel<<<grid, NT, smemBytes>>>(qt, ht, oh, kcE, nw,
                                         Ws1, bs1, Ws2, bs2,
                                         Wn1, bn1, Wn2, bn2,
                                         ea, We, be, Wa, ba,
                                         Wih, bih, Whh, bhh, Wp, bp, out);
}